// round 1
// baseline (speedup 1.0000x reference)
#include <cuda_runtime.h>
#include <cuda_bf16.h>
#include <cstdint>

#define BATCH 8192
#define DIM   2048   // U_DIM = V_DIM = LATENT
#define EPS   1e-5f
#define SLOPE 0.001f

// ---------------- scratch (__device__ globals; allocations are forbidden) ----
__device__ __nv_bfloat16 g_Au[(size_t)BATCH * DIM];   // LN(u) in bf16
__device__ __nv_bfloat16 g_Av[(size_t)BATCH * DIM];   // LN(v) in bf16
__device__ __nv_bfloat16 g_Wtu[(size_t)DIM * DIM];    // W_u^T  [n][k] bf16
__device__ __nv_bfloat16 g_Wtv[(size_t)DIM * DIM];    // W_v^T  [n][k] bf16

// ---------------- zero output ------------------------------------------------
__global__ void zero_kernel(float* __restrict__ out) {
    out[blockIdx.x * 256 + threadIdx.x] = 0.0f;
}

// ---------------- transpose + fp32->bf16 convert -----------------------------
// Wt[n][k] = bf16(W[k][n]);  W is [DIM][DIM] row-major (k rows, n cols)
__global__ void transpose_convert_kernel(const float* __restrict__ W,
                                         __nv_bfloat16* __restrict__ Wt) {
    __shared__ float tile[32][33];
    const int bx = blockIdx.x * 32;  // n base
    const int by = blockIdx.y * 32;  // k base
    const int tx = threadIdx.x, ty = threadIdx.y;  // 32 x 8
    #pragma unroll
    for (int j = 0; j < 32; j += 8)
        tile[ty + j][tx] = W[(size_t)(by + ty + j) * DIM + bx + tx];
    __syncthreads();
    #pragma unroll
    for (int j = 0; j < 32; j += 8)
        Wt[(size_t)(bx + ty + j) * DIM + by + tx] = __float2bfloat16(tile[tx][ty + j]);
}

// ---------------- LayerNorm (fp32 in -> bf16 out) ----------------------------
__global__ void ln_kernel(const float* __restrict__ x,
                          const float* __restrict__ w,
                          const float* __restrict__ b,
                          __nv_bfloat16* __restrict__ out) {
    const int row = blockIdx.x;
    const int t   = threadIdx.x;  // 256 threads
    const float4* xr = reinterpret_cast<const float4*>(x + (size_t)row * DIM);
    float4 v0 = xr[t];
    float4 v1 = xr[t + 256];
    float s = v0.x + v0.y + v0.z + v0.w + v1.x + v1.y + v1.z + v1.w;
    float q = v0.x*v0.x + v0.y*v0.y + v0.z*v0.z + v0.w*v0.w
            + v1.x*v1.x + v1.y*v1.y + v1.z*v1.z + v1.w*v1.w;
    #pragma unroll
    for (int off = 16; off; off >>= 1) {
        s += __shfl_xor_sync(0xffffffffu, s, off);
        q += __shfl_xor_sync(0xffffffffu, q, off);
    }
    __shared__ float ss[8], sq[8], stats[2];
    const int wid = t >> 5, lane = t & 31;
    if (lane == 0) { ss[wid] = s; sq[wid] = q; }
    __syncthreads();
    if (t == 0) {
        float S = 0.f, Q = 0.f;
        #pragma unroll
        for (int i = 0; i < 8; ++i) { S += ss[i]; Q += sq[i]; }
        float mu  = S * (1.0f / DIM);
        float var = Q * (1.0f / DIM) - mu * mu;
        stats[0] = mu;
        stats[1] = rsqrtf(var + EPS);
    }
    __syncthreads();
    const float mu = stats[0], rs = stats[1];
    const float4* wr = reinterpret_cast<const float4*>(w);
    const float4* br = reinterpret_cast<const float4*>(b);
    __nv_bfloat162* o = reinterpret_cast<__nv_bfloat162*>(out + (size_t)row * DIM);
    {
        float4 ww = wr[t], bb = br[t];
        o[2*t  ] = __floats2bfloat162_rn((v0.x-mu)*rs*ww.x + bb.x, (v0.y-mu)*rs*ww.y + bb.y);
        o[2*t+1] = __floats2bfloat162_rn((v0.z-mu)*rs*ww.z + bb.z, (v0.w-mu)*rs*ww.w + bb.w);
    }
    {
        float4 ww = wr[t+256], bb = br[t+256];
        o[2*(t+256)  ] = __floats2bfloat162_rn((v1.x-mu)*rs*ww.x + bb.x, (v1.y-mu)*rs*ww.y + bb.y);
        o[2*(t+256)+1] = __floats2bfloat162_rn((v1.z-mu)*rs*ww.z + bb.z, (v1.w-mu)*rs*ww.w + bb.w);
    }
}

// ---------------- fused dual GEMM + bias + LeakyReLU + dot reduce ------------
#define BM 128
#define BN 64
#define BK 32
#define KPAD 40   // bf16 elems per smem row (32 + 8 pad): conflict-free, 16B-aligned

__device__ __forceinline__ float leaky(float x) { return x >= 0.f ? x : SLOPE * x; }

#define MMA_BF16(C, A0, A1, A2, A3, B0, B1)                                   \
    asm volatile(                                                             \
        "mma.sync.aligned.m16n8k16.row.col.f32.bf16.bf16.f32 "                \
        "{%0,%1,%2,%3},{%4,%5,%6,%7},{%8,%9},{%0,%1,%2,%3};"                  \
        : "+f"(C[0]), "+f"(C[1]), "+f"(C[2]), "+f"(C[3])                      \
        : "r"(A0), "r"(A1), "r"(A2), "r"(A3), "r"(B0), "r"(B1))

__global__ void __launch_bounds__(256) fused_gemm_kernel(
    const float* __restrict__ bias_u, const float* __restrict__ bias_v,
    float* __restrict__ out) {
    extern __shared__ __nv_bfloat16 sm[];
    __nv_bfloat16* sAu = sm;                         // 2 * BM * KPAD
    __nv_bfloat16* sAv = sAu + 2 * BM * KPAD;
    __nv_bfloat16* sBu = sAv + 2 * BM * KPAD;        // 2 * BN * KPAD
    __nv_bfloat16* sBv = sBu + 2 * BN * KPAD;

    const int tid  = threadIdx.x;
    const int m0   = blockIdx.y * BM;
    const int n0   = blockIdx.x * BN;
    const int lane = tid & 31;
    const int g    = lane >> 2;   // groupID
    const int t4   = lane & 3;    // threadID_in_group
    const int warp = tid >> 5;
    const int wm   = (warp >> 1) * 32;  // warp m offset in block (0..96)
    const int wn   = (warp & 1) * 32;   // warp n offset in block (0 or 32)

    // global-load indexing: A tile has 512 uint4 chunks (2/thread), B tile 256 (1/thread)
    const int ac0 = tid, ac1 = tid + 256;
    const int a0r = ac0 >> 2, a0c = (ac0 & 3) * 8;
    const int a1r = ac1 >> 2, a1c = (ac1 & 3) * 8;
    const int br_ = tid >> 2, bc_ = (tid & 3) * 8;

    float cu[2][4][4], cv[2][4][4];
    #pragma unroll
    for (int i = 0; i < 2; ++i)
        #pragma unroll
        for (int j = 0; j < 4; ++j)
            #pragma unroll
            for (int k = 0; k < 4; ++k) { cu[i][j][k] = 0.f; cv[i][j][k] = 0.f; }

    auto gload = [&](int k0, uint4* rAu, uint4* rAv, uint4& rBu, uint4& rBv) {
        rAu[0] = *reinterpret_cast<const uint4*>(&g_Au[(size_t)(m0 + a0r) * DIM + k0 + a0c]);
        rAu[1] = *reinterpret_cast<const uint4*>(&g_Au[(size_t)(m0 + a1r) * DIM + k0 + a1c]);
        rAv[0] = *reinterpret_cast<const uint4*>(&g_Av[(size_t)(m0 + a0r) * DIM + k0 + a0c]);
        rAv[1] = *reinterpret_cast<const uint4*>(&g_Av[(size_t)(m0 + a1r) * DIM + k0 + a1c]);
        rBu    = *reinterpret_cast<const uint4*>(&g_Wtu[(size_t)(n0 + br_) * DIM + k0 + bc_]);
        rBv    = *reinterpret_cast<const uint4*>(&g_Wtv[(size_t)(n0 + br_) * DIM + k0 + bc_]);
    };
    auto sstore = [&](int buf, const uint4* rAu, const uint4* rAv,
                      const uint4& rBu, const uint4& rBv) {
        __nv_bfloat16* au = sAu + buf * BM * KPAD;
        __nv_bfloat16* av = sAv + buf * BM * KPAD;
        __nv_bfloat16* pu = sBu + buf * BN * KPAD;
        __nv_bfloat16* pv = sBv + buf * BN * KPAD;
        *reinterpret_cast<uint4*>(&au[a0r * KPAD + a0c]) = rAu[0];
        *reinterpret_cast<uint4*>(&au[a1r * KPAD + a1c]) = rAu[1];
        *reinterpret_cast<uint4*>(&av[a0r * KPAD + a0c]) = rAv[0];
        *reinterpret_cast<uint4*>(&av[a1r * KPAD + a1c]) = rAv[1];
        *reinterpret_cast<uint4*>(&pu[br_ * KPAD + bc_]) = rBu;
        *reinterpret_cast<uint4*>(&pv[br_ * KPAD + bc_]) = rBv;
    };

    // prologue: tile 0 -> buffer 0
    {
        uint4 rAu[2], rAv[2], rBu, rBv;
        gload(0, rAu, rAv, rBu, rBv);
        sstore(0, rAu, rAv, rBu, rBv);
    }

    const int KT = DIM / BK;
    for (int kt = 0; kt < KT; ++kt) {
        __syncthreads();
        const int cur = kt & 1, nxt = cur ^ 1;
        const bool pf = (kt + 1 < KT);
        uint4 rAu[2], rAv[2], rBu, rBv;
        if (pf) gload((kt + 1) * BK, rAu, rAv, rBu, rBv);

        const __nv_bfloat16* cAu = sAu + cur * BM * KPAD;
        const __nv_bfloat16* cAv = sAv + cur * BM * KPAD;
        const __nv_bfloat16* cBu = sBu + cur * BN * KPAD;
        const __nv_bfloat16* cBv = sBv + cur * BN * KPAD;

        #pragma unroll
        for (int ks = 0; ks < BK; ks += 16) {
            uint32_t fbu[4][2], fbv[4][2];
            #pragma unroll
            for (int nt = 0; nt < 4; ++nt) {
                const __nv_bfloat16* pu = cBu + (wn + nt * 8 + g) * KPAD + ks + 2 * t4;
                const __nv_bfloat16* pv = cBv + (wn + nt * 8 + g) * KPAD + ks + 2 * t4;
                fbu[nt][0] = *reinterpret_cast<const uint32_t*>(pu);
                fbu[nt][1] = *reinterpret_cast<const uint32_t*>(pu + 8);
                fbv[nt][0] = *reinterpret_cast<const uint32_t*>(pv);
                fbv[nt][1] = *reinterpret_cast<const uint32_t*>(pv + 8);
            }
            #pragma unroll
            for (int mt = 0; mt < 2; ++mt) {
                const __nv_bfloat16* pa = cAu + (wm + mt * 16 + g) * KPAD + ks + 2 * t4;
                uint32_t a0 = *reinterpret_cast<const uint32_t*>(pa);
                uint32_t a1 = *reinterpret_cast<const uint32_t*>(pa + 8 * KPAD);
                uint32_t a2 = *reinterpret_cast<const uint32_t*>(pa + 8);
                uint32_t a3 = *reinterpret_cast<const uint32_t*>(pa + 8 * KPAD + 8);
                #pragma unroll
                for (int nt = 0; nt < 4; ++nt)
                    MMA_BF16(cu[mt][nt], a0, a1, a2, a3, fbu[nt][0], fbu[nt][1]);

                const __nv_bfloat16* pb = cAv + (wm + mt * 16 + g) * KPAD + ks + 2 * t4;
                uint32_t c0 = *reinterpret_cast<const uint32_t*>(pb);
                uint32_t c1 = *reinterpret_cast<const uint32_t*>(pb + 8 * KPAD);
                uint32_t c2 = *reinterpret_cast<const uint32_t*>(pb + 8);
                uint32_t c3 = *reinterpret_cast<const uint32_t*>(pb + 8 * KPAD + 8);
                #pragma unroll
                for (int nt = 0; nt < 4; ++nt)
                    MMA_BF16(cv[mt][nt], c0, c1, c2, c3, fbv[nt][0], fbv[nt][1]);
            }
        }
        if (pf) sstore(nxt, rAu, rAv, rBu, rBv);
    }

    // epilogue: bias + LeakyReLU on both towers, elementwise product, row reduce
    #pragma unroll
    for (int mt = 0; mt < 2; ++mt) {
        float p0 = 0.f, p1 = 0.f;
        #pragma unroll
        for (int nt = 0; nt < 4; ++nt) {
            const int ncol = n0 + wn + nt * 8 + 2 * t4;
            const float bu0 = bias_u[ncol], bu1 = bias_u[ncol + 1];
            const float bv0 = bias_v[ncol], bv1 = bias_v[ncol + 1];
            const float hu0 = leaky(cu[mt][nt][0] + bu0);
            const float hu1 = leaky(cu[mt][nt][1] + bu1);
            const float hu2 = leaky(cu[mt][nt][2] + bu0);
            const float hu3 = leaky(cu[mt][nt][3] + bu1);
            const float hv0 = leaky(cv[mt][nt][0] + bv0);
            const float hv1 = leaky(cv[mt][nt][1] + bv1);
            const float hv2 = leaky(cv[mt][nt][2] + bv0);
            const float hv3 = leaky(cv[mt][nt][3] + bv1);
            p0 += hu0 * hv0 + hu1 * hv1;
            p1 += hu2 * hv2 + hu3 * hv3;
        }
        p0 += __shfl_xor_sync(0xffffffffu, p0, 1);
        p0 += __shfl_xor_sync(0xffffffffu, p0, 2);
        p1 += __shfl_xor_sync(0xffffffffu, p1, 1);
        p1 += __shfl_xor_sync(0xffffffffu, p1, 2);
        if (t4 == 0) {
            const int r = m0 + wm + mt * 16 + g;
            atomicAdd(&out[r], p0);
            atomicAdd(&out[r + 8], p1);
        }
    }
}

// ---------------- launch -----------------------------------------------------
extern "C" void kernel_launch(void* const* d_in, const int* in_sizes, int n_in,
                              void* d_out, int out_size) {
    (void)in_sizes; (void)n_in; (void)out_size;
    const float* u      = (const float*)d_in[0];
    const float* v      = (const float*)d_in[1];
    const float* ln_u_w = (const float*)d_in[2];
    const float* ln_u_b = (const float*)d_in[3];
    const float* ln_v_w = (const float*)d_in[4];
    const float* ln_v_b = (const float*)d_in[5];
    const float* W_u    = (const float*)d_in[6];
    const float* b_u    = (const float*)d_in[7];
    const float* W_v    = (const float*)d_in[8];
    const float* b_v    = (const float*)d_in[9];
    float* out = (float*)d_out;

    void *pAu, *pAv, *pWtu, *pWtv;
    cudaGetSymbolAddress(&pAu, g_Au);
    cudaGetSymbolAddress(&pAv, g_Av);
    cudaGetSymbolAddress(&pWtu, g_Wtu);
    cudaGetSymbolAddress(&pWtv, g_Wtv);

    zero_kernel<<<BATCH / 256, 256>>>(out);

    dim3 tgrid(DIM / 32, DIM / 32), tblk(32, 8);
    transpose_convert_kernel<<<tgrid, tblk>>>(W_u, (__nv_bfloat16*)pWtu);
    transpose_convert_kernel<<<tgrid, tblk>>>(W_v, (__nv_bfloat16*)pWtv);

    ln_kernel<<<BATCH, 256>>>(u, ln_u_w, ln_u_b, (__nv_bfloat16*)pAu);
    ln_kernel<<<BATCH, 256>>>(v, ln_v_w, ln_v_b, (__nv_bfloat16*)pAv);

    const int smem_bytes = (2 * BM * KPAD * 2 + 2 * BN * KPAD * 2) * (int)sizeof(__nv_bfloat16);
    cudaFuncSetAttribute(fused_gemm_kernel,
                         cudaFuncAttributeMaxDynamicSharedMemorySize, smem_bytes);
    fused_gemm_kernel<<<dim3(DIM / BN, BATCH / BM), 256, smem_bytes>>>(b_u, b_v, out);
}

// round 3
// speedup vs baseline: 1.7185x; 1.7185x over previous
#include <cuda_runtime.h>
#include <cuda_bf16.h>
#include <cstdint>

#define BATCH 8192
#define DIM   2048
#define EPS   1e-5f
#define SLOPE 0.001f

// ---- GEMM tiling ----
#define BM 128
#define BN 128
#define BK 64
#define KT_ITERS (DIM / BK)        // 32
#define STAGES 3
#define TILE_BYTES 16384           // 128 rows x 128 bytes
#define STAGE_BYTES (4 * TILE_BYTES)  // Au, Av, Bu, Bv
#define SMEM_DYN (STAGES * STAGE_BYTES + 1024)

// ---------------- scratch (__device__ globals; allocations forbidden) --------
__device__ __align__(1024) __nv_bfloat16 g_Au[(size_t)BATCH * DIM];
__device__ __align__(1024) __nv_bfloat16 g_Av[(size_t)BATCH * DIM];
__device__ __align__(1024) __nv_bfloat16 g_Wtu[(size_t)DIM * DIM];   // [n][k]
__device__ __align__(1024) __nv_bfloat16 g_Wtv[(size_t)DIM * DIM];   // [n][k]

// ---------------- helpers ----------------------------------------------------
__device__ __forceinline__ uint32_t smem_u32(const void* p) {
    uint32_t a;
    asm("{ .reg .u64 t; cvta.to.shared.u64 t, %1; cvt.u32.u64 %0, t; }" : "=r"(a) : "l"(p));
    return a;
}
#define SW128(off) ((off) ^ (((off) >> 3) & 0x70))

#define CP_ASYNC16(saddr, gptr) \
    asm volatile("cp.async.cg.shared.global [%0], [%1], 16;" :: "r"(saddr), "l"(gptr))
#define CP_COMMIT() asm volatile("cp.async.commit_group;" ::: "memory")
#define CP_WAIT1()  asm volatile("cp.async.wait_group 1;" ::: "memory")

#define LDSM4(r0, r1, r2, r3, addr)                                            \
    asm volatile("ldmatrix.sync.aligned.m8n8.x4.shared.b16 {%0,%1,%2,%3}, [%4];" \
                 : "=r"(r0), "=r"(r1), "=r"(r2), "=r"(r3) : "r"(addr))

#define MMA_BF16(C, A0, A1, A2, A3, B0, B1)                                   \
    asm volatile(                                                             \
        "mma.sync.aligned.m16n8k16.row.col.f32.bf16.bf16.f32 "                \
        "{%0,%1,%2,%3},{%4,%5,%6,%7},{%8,%9},{%0,%1,%2,%3};"                  \
        : "+f"(C[0]), "+f"(C[1]), "+f"(C[2]), "+f"(C[3])                      \
        : "r"(A0), "r"(A1), "r"(A2), "r"(A3), "r"(B0), "r"(B1))

__device__ __forceinline__ float leaky(float x) { return x >= 0.f ? x : SLOPE * x; }

// ---------------- small kernels ----------------------------------------------
__global__ void zero_kernel(float* __restrict__ out) {
    out[blockIdx.x * 256 + threadIdx.x] = 0.0f;
}

__global__ void transpose_convert_kernel(const float* __restrict__ W,
                                         __nv_bfloat16* __restrict__ Wt) {
    __shared__ float tile[32][33];
    const int bx = blockIdx.x * 32, by = blockIdx.y * 32;
    const int tx = threadIdx.x, ty = threadIdx.y;
    #pragma unroll
    for (int j = 0; j < 32; j += 8)
        tile[ty + j][tx] = W[(size_t)(by + ty + j) * DIM + bx + tx];
    __syncthreads();
    #pragma unroll
    for (int j = 0; j < 32; j += 8)
        Wt[(size_t)(bx + ty + j) * DIM + by + tx] = __float2bfloat16(tile[tx][ty + j]);
}

// 512 threads, one float4 per thread: pure streaming LayerNorm
__global__ void ln_kernel(const float* __restrict__ x,
                          const float* __restrict__ w,
                          const float* __restrict__ b,
                          __nv_bfloat16* __restrict__ out) {
    const int row = blockIdx.x;
    const int t   = threadIdx.x;   // 512
    const float4* xr = reinterpret_cast<const float4*>(x + (size_t)row * DIM);
    float4 v = xr[t];
    float s = v.x + v.y + v.z + v.w;
    float q = v.x*v.x + v.y*v.y + v.z*v.z + v.w*v.w;
    #pragma unroll
    for (int off = 16; off; off >>= 1) {
        s += __shfl_xor_sync(0xffffffffu, s, off);
        q += __shfl_xor_sync(0xffffffffu, q, off);
    }
    __shared__ float ss[16], sq[16], stats[2];
    const int wid = t >> 5, lane = t & 31;
    if (lane == 0) { ss[wid] = s; sq[wid] = q; }
    __syncthreads();
    if (t < 32) {
        float S = (t < 16) ? ss[t] : 0.f;
        float Q = (t < 16) ? sq[t] : 0.f;
        #pragma unroll
        for (int off = 8; off; off >>= 1) {
            S += __shfl_xor_sync(0xffffffffu, S, off);
            Q += __shfl_xor_sync(0xffffffffu, Q, off);
        }
        if (t == 0) {
            float mu  = S * (1.0f / DIM);
            float var = Q * (1.0f / DIM) - mu * mu;
            stats[0] = mu;
            stats[1] = rsqrtf(var + EPS);
        }
    }
    __syncthreads();
    const float mu = stats[0], rs = stats[1];
    const float4 ww = reinterpret_cast<const float4*>(w)[t];
    const float4 bb = reinterpret_cast<const float4*>(b)[t];
    __nv_bfloat162* o = reinterpret_cast<__nv_bfloat162*>(out + (size_t)row * DIM);
    o[2*t  ] = __floats2bfloat162_rn((v.x-mu)*rs*ww.x + bb.x, (v.y-mu)*rs*ww.y + bb.y);
    o[2*t+1] = __floats2bfloat162_rn((v.z-mu)*rs*ww.z + bb.z, (v.w-mu)*rs*ww.w + bb.w);
}

// ---------------- fused dual GEMM + bias + LeakyReLU + dot reduce ------------
__global__ void __launch_bounds__(256, 1) fused_gemm_kernel(
    const float* __restrict__ bias_u, const float* __restrict__ bias_v,
    float* __restrict__ out) {
    extern __shared__ char smem[];
    const uint32_t sbase = (smem_u32(smem) + 1023u) & ~1023u;
    const int tid  = threadIdx.x;
    const int warp = tid >> 5;
    const int lane = tid & 31;
    const int g    = lane >> 2;
    const int t4   = lane & 3;
    const int m0   = blockIdx.y * BM;
    const int n0   = blockIdx.x * BN;
    const int wm   = (warp & 3) * 32;   // 4 warps along M
    const int wn   = (warp >> 2) * 64;  // 2 warps along N

    float cu[2][8][4], cv[2][8][4];
    #pragma unroll
    for (int i = 0; i < 2; ++i)
        #pragma unroll
        for (int j = 0; j < 8; ++j)
            #pragma unroll
            for (int k = 0; k < 4; ++k) { cu[i][j][k] = 0.f; cv[i][j][k] = 0.f; }

    auto load_stage = [&](int s, int chunk) {
        const uint32_t stb = sbase + s * STAGE_BYTES;
        const size_t kg = (size_t)chunk * BK;
        #pragma unroll
        for (int c = tid; c < 1024; c += 256) {   // 128 rows x 8 x 16B chunks per tile
            const int r = c >> 3, bo = (c & 7) * 16;
            const uint32_t so = SW128((uint32_t)(r * 128 + bo));
            const size_t ga = (size_t)(m0 + r) * DIM + kg + (bo >> 1);
            const size_t gb = (size_t)(n0 + r) * DIM + kg + (bo >> 1);
            CP_ASYNC16(stb + so,                  &g_Au[ga]);
            CP_ASYNC16(stb + TILE_BYTES + so,     &g_Av[ga]);
            CP_ASYNC16(stb + 2 * TILE_BYTES + so, &g_Wtu[gb]);
            CP_ASYNC16(stb + 3 * TILE_BYTES + so, &g_Wtv[gb]);
        }
    };

    // ldmatrix per-lane address components
    const int a_row = lane & 15;             // row within 16-row A tile
    const int a_kb  = (lane >> 4) << 4;      // 0 or 16 bytes (k half)
    const int b_row = (lane & 7) + ((lane >> 4) << 3);  // row within 16-row B tile
    const int b_kb  = ((lane >> 3) & 1) << 4;           // 0 or 16 bytes

    load_stage(0, 0); CP_COMMIT();
    load_stage(1, 1); CP_COMMIT();

    for (int kt = 0; kt < KT_ITERS; ++kt) {
        CP_WAIT1();
        __syncthreads();
        if (kt + 2 < KT_ITERS) load_stage((kt + 2) % STAGES, kt + 2);
        CP_COMMIT();

        const uint32_t stb = sbase + (kt % STAGES) * STAGE_BYTES;
        #pragma unroll
        for (int ks = 0; ks < 4; ++ks) {
            uint32_t bu[8][2], bv[8][2];
            #pragma unroll
            for (int t = 0; t < 4; ++t) {
                const int nrow = wn + t * 16 + b_row;
                const uint32_t off = SW128((uint32_t)(nrow * 128 + ks * 32 + b_kb));
                uint32_t r0, r1, r2, r3;
                LDSM4(r0, r1, r2, r3, stb + 2 * TILE_BYTES + off);
                bu[2*t][0] = r0; bu[2*t][1] = r1; bu[2*t+1][0] = r2; bu[2*t+1][1] = r3;
                LDSM4(r0, r1, r2, r3, stb + 3 * TILE_BYTES + off);
                bv[2*t][0] = r0; bv[2*t][1] = r1; bv[2*t+1][0] = r2; bv[2*t+1][1] = r3;
            }
            #pragma unroll
            for (int mt = 0; mt < 2; ++mt) {
                const int arow = wm + mt * 16 + a_row;
                const uint32_t off = SW128((uint32_t)(arow * 128 + ks * 32 + a_kb));
                uint32_t a0, a1, a2, a3;
                LDSM4(a0, a1, a2, a3, stb + off);
                #pragma unroll
                for (int j = 0; j < 8; ++j)
                    MMA_BF16(cu[mt][j], a0, a1, a2, a3, bu[j][0], bu[j][1]);
                LDSM4(a0, a1, a2, a3, stb + TILE_BYTES + off);
                #pragma unroll
                for (int j = 0; j < 8; ++j)
                    MMA_BF16(cv[mt][j], a0, a1, a2, a3, bv[j][0], bv[j][1]);
            }
        }
    }

    // epilogue: bias + LeakyReLU, elementwise product, row reduce
    float p0[2] = {0.f, 0.f}, p1[2] = {0.f, 0.f};
    #pragma unroll
    for (int j = 0; j < 8; ++j) {
        const int ncol = n0 + wn + j * 8 + 2 * t4;
        const float bu0 = bias_u[ncol], bu1 = bias_u[ncol + 1];
        const float bv0 = bias_v[ncol], bv1 = bias_v[ncol + 1];
        #pragma unroll
        for (int mt = 0; mt < 2; ++mt) {
            const float hu0 = leaky(cu[mt][j][0] + bu0);
            const float hu1 = leaky(cu[mt][j][1] + bu1);
            const float hv0 = leaky(cv[mt][j][0] + bv0);
            const float hv1 = leaky(cv[mt][j][1] + bv1);
            p0[mt] += hu0 * hv0 + hu1 * hv1;
            const float hu2 = leaky(cu[mt][j][2] + bu0);
            const float hu3 = leaky(cu[mt][j][3] + bu1);
            const float hv2 = leaky(cv[mt][j][2] + bv0);
            const float hv3 = leaky(cv[mt][j][3] + bv1);
            p1[mt] += hu2 * hv2 + hu3 * hv3;
        }
    }
    #pragma unroll
    for (int mt = 0; mt < 2; ++mt) {
        float a = p0[mt], b = p1[mt];
        a += __shfl_xor_sync(0xffffffffu, a, 1);
        a += __shfl_xor_sync(0xffffffffu, a, 2);
        b += __shfl_xor_sync(0xffffffffu, b, 1);
        b += __shfl_xor_sync(0xffffffffu, b, 2);
        if (t4 == 0) {
            const int r = m0 + wm + mt * 16 + g;
            atomicAdd(&out[r], a);
            atomicAdd(&out[r + 8], b);
        }
    }
}

// ---------------- launch -----------------------------------------------------
extern "C" void kernel_launch(void* const* d_in, const int* in_sizes, int n_in,
                              void* d_out, int out_size) {
    (void)in_sizes; (void)n_in; (void)out_size;
    const float* u      = (const float*)d_in[0];
    const float* v      = (const float*)d_in[1];
    const float* ln_u_w = (const float*)d_in[2];
    const float* ln_u_b = (const float*)d_in[3];
    const float* ln_v_w = (const float*)d_in[4];
    const float* ln_v_b = (const float*)d_in[5];
    const float* W_u    = (const float*)d_in[6];
    const float* b_u    = (const float*)d_in[7];
    const float* W_v    = (const float*)d_in[8];
    const float* b_v    = (const float*)d_in[9];
    float* out = (float*)d_out;

    void *pAu, *pAv, *pWtu, *pWtv;
    cudaGetSymbolAddress(&pAu, g_Au);
    cudaGetSymbolAddress(&pAv, g_Av);
    cudaGetSymbolAddress(&pWtu, g_Wtu);
    cudaGetSymbolAddress(&pWtv, g_Wtv);

    zero_kernel<<<BATCH / 256, 256>>>(out);

    dim3 tgrid(DIM / 32, DIM / 32), tblk(32, 8);
    transpose_convert_kernel<<<tgrid, tblk>>>(W_u, (__nv_bfloat16*)pWtu);
    transpose_convert_kernel<<<tgrid, tblk>>>(W_v, (__nv_bfloat16*)pWtv);

    ln_kernel<<<BATCH, 512>>>(u, ln_u_w, ln_u_b, (__nv_bfloat16*)pAu);
    ln_kernel<<<BATCH, 512>>>(v, ln_v_w, ln_v_b, (__nv_bfloat16*)pAv);

    cudaFuncSetAttribute(fused_gemm_kernel,
                         cudaFuncAttributeMaxDynamicSharedMemorySize, SMEM_DYN);
    fused_gemm_kernel<<<dim3(DIM / BN, BATCH / BM), 256, SMEM_DYN>>>(b_u, b_v, out);
}

// round 4
// speedup vs baseline: 1.7715x; 1.0309x over previous
#include <cuda_runtime.h>
#include <cuda_bf16.h>
#include <cstdint>

#define BATCH 8192
#define DIM   2048
#define EPS   1e-5f
#define SLOPE 0.001f

// ---- GEMM tiling ----
#define BM 128
#define BN 128
#define BK 64
#define KT_ITERS (DIM / BK)            // 32
#define STAGES 3
#define TILE_BYTES 16384               // 128 rows x 128 bytes
#define STAGE_BYTES (4 * TILE_BYTES)   // Au, Av, Bu, Bv
#define SMEM_DYN (STAGES * STAGE_BYTES + 1024)

// ---------------- scratch (__device__ globals; allocations forbidden) --------
__device__ __align__(1024) __nv_bfloat16 g_Au[(size_t)BATCH * DIM];
__device__ __align__(1024) __nv_bfloat16 g_Av[(size_t)BATCH * DIM];
__device__ __align__(1024) __nv_bfloat16 g_Wtu[(size_t)DIM * DIM];   // [n][k]
__device__ __align__(1024) __nv_bfloat16 g_Wtv[(size_t)DIM * DIM];   // [n][k]

// ---------------- helpers ----------------------------------------------------
__device__ __forceinline__ uint32_t smem_u32(const void* p) {
    uint32_t a;
    asm("{ .reg .u64 t; cvta.to.shared.u64 t, %1; cvt.u32.u64 %0, t; }" : "=r"(a) : "l"(p));
    return a;
}
#define SW128(off) ((off) ^ (((off) >> 3) & 0x70))

#define CP_ASYNC16(saddr, gptr) \
    asm volatile("cp.async.cg.shared.global [%0], [%1], 16;" :: "r"(saddr), "l"(gptr))
#define CP_COMMIT() asm volatile("cp.async.commit_group;" ::: "memory")
#define CP_WAIT1()  asm volatile("cp.async.wait_group 1;" ::: "memory")

#define LDSM4(r0, r1, r2, r3, addr)                                            \
    asm volatile("ldmatrix.sync.aligned.m8n8.x4.shared.b16 {%0,%1,%2,%3}, [%4];" \
                 : "=r"(r0), "=r"(r1), "=r"(r2), "=r"(r3) : "r"(addr))

#define MMA_BF16(C, A0, A1, A2, A3, B0, B1)                                   \
    asm volatile(                                                             \
        "mma.sync.aligned.m16n8k16.row.col.f32.bf16.bf16.f32 "                \
        "{%0,%1,%2,%3},{%4,%5,%6,%7},{%8,%9},{%0,%1,%2,%3};"                  \
        : "+f"(C[0]), "+f"(C[1]), "+f"(C[2]), "+f"(C[3])                      \
        : "r"(A0), "r"(A1), "r"(A2), "r"(A3), "r"(B0), "r"(B1))

__device__ __forceinline__ float leaky(float x) { return x >= 0.f ? x : SLOPE * x; }

// ---------------- small kernels ----------------------------------------------
__global__ void zero_kernel(float* __restrict__ out) {
    out[blockIdx.x * 256 + threadIdx.x] = 0.0f;
}

__global__ void transpose_convert_kernel(const float* __restrict__ W,
                                         __nv_bfloat16* __restrict__ Wt) {
    __shared__ float tile[32][33];
    const int bx = blockIdx.x * 32, by = blockIdx.y * 32;
    const int tx = threadIdx.x, ty = threadIdx.y;
    #pragma unroll
    for (int j = 0; j < 32; j += 8)
        tile[ty + j][tx] = W[(size_t)(by + ty + j) * DIM + bx + tx];
    __syncthreads();
    #pragma unroll
    for (int j = 0; j < 32; j += 8)
        Wt[(size_t)(bx + ty + j) * DIM + by + tx] = __float2bfloat16(tile[tx][ty + j]);
}

// 256 threads, two float4 per thread (measured faster than 512-thr variant)
__global__ void ln_kernel(const float* __restrict__ x,
                          const float* __restrict__ w,
                          const float* __restrict__ b,
                          __nv_bfloat16* __restrict__ out) {
    const int row = blockIdx.x;
    const int t   = threadIdx.x;
    const float4* xr = reinterpret_cast<const float4*>(x + (size_t)row * DIM);
    float4 v0 = xr[t];
    float4 v1 = xr[t + 256];
    float s = v0.x + v0.y + v0.z + v0.w + v1.x + v1.y + v1.z + v1.w;
    float q = v0.x*v0.x + v0.y*v0.y + v0.z*v0.z + v0.w*v0.w
            + v1.x*v1.x + v1.y*v1.y + v1.z*v1.z + v1.w*v1.w;
    #pragma unroll
    for (int off = 16; off; off >>= 1) {
        s += __shfl_xor_sync(0xffffffffu, s, off);
        q += __shfl_xor_sync(0xffffffffu, q, off);
    }
    __shared__ float ss[8], sq[8], stats[2];
    const int wid = t >> 5, lane = t & 31;
    if (lane == 0) { ss[wid] = s; sq[wid] = q; }
    __syncthreads();
    if (t == 0) {
        float S = 0.f, Q = 0.f;
        #pragma unroll
        for (int i = 0; i < 8; ++i) { S += ss[i]; Q += sq[i]; }
        float mu  = S * (1.0f / DIM);
        float var = Q * (1.0f / DIM) - mu * mu;
        stats[0] = mu;
        stats[1] = rsqrtf(var + EPS);
    }
    __syncthreads();
    const float mu = stats[0], rs = stats[1];
    const float4* wr = reinterpret_cast<const float4*>(w);
    const float4* br = reinterpret_cast<const float4*>(b);
    __nv_bfloat162* o = reinterpret_cast<__nv_bfloat162*>(out + (size_t)row * DIM);
    {
        float4 ww = wr[t], bb = br[t];
        o[2*t  ] = __floats2bfloat162_rn((v0.x-mu)*rs*ww.x + bb.x, (v0.y-mu)*rs*ww.y + bb.y);
        o[2*t+1] = __floats2bfloat162_rn((v0.z-mu)*rs*ww.z + bb.z, (v0.w-mu)*rs*ww.w + bb.w);
    }
    {
        float4 ww = wr[t+256], bb = br[t+256];
        o[2*(t+256)  ] = __floats2bfloat162_rn((v1.x-mu)*rs*ww.x + bb.x, (v1.y-mu)*rs*ww.y + bb.y);
        o[2*(t+256)+1] = __floats2bfloat162_rn((v1.z-mu)*rs*ww.z + bb.z, (v1.w-mu)*rs*ww.w + bb.w);
    }
}

// ---------------- fused dual GEMM + bias + LeakyReLU + dot reduce ------------
// 512 threads. Warps 0-7: u tower; warps 8-15: v tower. Warp tile 32x64.
__global__ void __launch_bounds__(512, 1) fused_gemm_kernel(
    const float* __restrict__ bias_u, const float* __restrict__ bias_v,
    float* __restrict__ out) {
    extern __shared__ char smem[];
    const uint32_t sbase = (smem_u32(smem) + 1023u) & ~1023u;
    const int tid   = threadIdx.x;
    const int warp  = tid >> 5;
    const int lane  = tid & 31;
    const int g     = lane >> 2;
    const int t4    = lane & 3;
    const int tower = warp >> 3;         // 0 = u, 1 = v
    const int wq    = warp & 7;
    const int wm    = (wq & 3) * 32;     // 4 warps along M
    const int wn    = (wq >> 2) * 64;    // 2 warps along N
    const int m0    = blockIdx.y * BM;
    const int n0    = blockIdx.x * BN;

    // per-tower tile bases inside a stage: [Au, Av, Bu, Bv]
    const uint32_t a_tile = tower * TILE_BYTES;
    const uint32_t b_tile = 2 * TILE_BYTES + tower * TILE_BYTES;

    float acc[2][8][4];
    #pragma unroll
    for (int i = 0; i < 2; ++i)
        #pragma unroll
        for (int j = 0; j < 8; ++j)
            #pragma unroll
            for (int k = 0; k < 4; ++k) acc[i][j][k] = 0.f;

    auto load_stage = [&](int s, int chunk) {
        const uint32_t stb = sbase + s * STAGE_BYTES;
        const size_t kg = (size_t)chunk * BK;
        #pragma unroll
        for (int c = tid; c < 1024; c += 512) {   // per tile: 128 rows x 8 x 16B
            const int r = c >> 3, bo = (c & 7) * 16;
            const uint32_t so = SW128((uint32_t)(r * 128 + bo));
            const size_t ga = (size_t)(m0 + r) * DIM + kg + (bo >> 1);
            const size_t gb = (size_t)(n0 + r) * DIM + kg + (bo >> 1);
            CP_ASYNC16(stb + so,                  &g_Au[ga]);
            CP_ASYNC16(stb + TILE_BYTES + so,     &g_Av[ga]);
            CP_ASYNC16(stb + 2 * TILE_BYTES + so, &g_Wtu[gb]);
            CP_ASYNC16(stb + 3 * TILE_BYTES + so, &g_Wtv[gb]);
        }
    };

    // ldmatrix per-lane address components
    const int a_row = lane & 15;
    const int a_kb  = (lane >> 4) << 4;
    const int b_row = (lane & 7) + ((lane >> 4) << 3);
    const int b_kb  = ((lane >> 3) & 1) << 4;

    load_stage(0, 0); CP_COMMIT();
    load_stage(1, 1); CP_COMMIT();

    for (int kt = 0; kt < KT_ITERS; ++kt) {
        CP_WAIT1();
        __syncthreads();
        if (kt + 2 < KT_ITERS) load_stage((kt + 2) % STAGES, kt + 2);
        CP_COMMIT();

        const uint32_t stb = sbase + (kt % STAGES) * STAGE_BYTES;
        #pragma unroll
        for (int ks = 0; ks < 4; ++ks) {
            uint32_t bf[8][2];
            #pragma unroll
            for (int t = 0; t < 4; ++t) {
                const int nrow = wn + t * 16 + b_row;
                const uint32_t off = SW128((uint32_t)(nrow * 128 + ks * 32 + b_kb));
                uint32_t r0, r1, r2, r3;
                LDSM4(r0, r1, r2, r3, stb + b_tile + off);
                bf[2*t][0] = r0; bf[2*t][1] = r1; bf[2*t+1][0] = r2; bf[2*t+1][1] = r3;
            }
            #pragma unroll
            for (int mt = 0; mt < 2; ++mt) {
                const int arow = wm + mt * 16 + a_row;
                const uint32_t off = SW128((uint32_t)(arow * 128 + ks * 32 + a_kb));
                uint32_t a0, a1, a2, a3;
                LDSM4(a0, a1, a2, a3, stb + a_tile + off);
                #pragma unroll
                for (int j = 0; j < 8; ++j)
                    MMA_BF16(acc[mt][j], a0, a1, a2, a3, bf[j][0], bf[j][1]);
            }
        }
    }

    // ---------------- epilogue ----------------
    // v-warps: hv = leaky(acc + bias_v) -> smem in native fragment order.
    // u-warps: hu = leaky(acc + bias_u), read matching hv slot, product, reduce.
    float* xbuf = reinterpret_cast<float*>(smem);  // 8 warps * 32 lanes * 64 = 64KB
    __syncthreads();   // all MMA reads of stage smem done before reuse

    if (tower == 1) {
        float* dst = xbuf + (wq * 64) * 32 + lane;   // [wq][reg][lane]
        #pragma unroll
        for (int mt = 0; mt < 2; ++mt)
            #pragma unroll
            for (int j = 0; j < 8; ++j) {
                const int ncol = n0 + wn + j * 8 + 2 * t4;
                const float b0 = bias_v[ncol], b1 = bias_v[ncol + 1];
                const int r = mt * 32 + j * 4;
                dst[(r + 0) * 32] = leaky(acc[mt][j][0] + b0);
                dst[(r + 1) * 32] = leaky(acc[mt][j][1] + b1);
                dst[(r + 2) * 32] = leaky(acc[mt][j][2] + b0);
                dst[(r + 3) * 32] = leaky(acc[mt][j][3] + b1);
            }
    }
    __syncthreads();
    if (tower == 0) {
        const float* src = xbuf + (wq * 64) * 32 + lane;
        float p[2][2] = {{0.f, 0.f}, {0.f, 0.f}};
        #pragma unroll
        for (int mt = 0; mt < 2; ++mt)
            #pragma unroll
            for (int j = 0; j < 8; ++j) {
                const int ncol = n0 + wn + j * 8 + 2 * t4;
                const float b0 = bias_u[ncol], b1 = bias_u[ncol + 1];
                const int r = mt * 32 + j * 4;
                p[mt][0] += leaky(acc[mt][j][0] + b0) * src[(r + 0) * 32];
                p[mt][0] += leaky(acc[mt][j][1] + b1) * src[(r + 1) * 32];
                p[mt][1] += leaky(acc[mt][j][2] + b0) * src[(r + 2) * 32];
                p[mt][1] += leaky(acc[mt][j][3] + b1) * src[(r + 3) * 32];
            }
        #pragma unroll
        for (int mt = 0; mt < 2; ++mt) {
            float a = p[mt][0], b = p[mt][1];
            a += __shfl_xor_sync(0xffffffffu, a, 1);
            a += __shfl_xor_sync(0xffffffffu, a, 2);
            b += __shfl_xor_sync(0xffffffffu, b, 1);
            b += __shfl_xor_sync(0xffffffffu, b, 2);
            if (t4 == 0) {
                const int r = m0 + wm + mt * 16 + g;
                atomicAdd(&out[r], a);
                atomicAdd(&out[r + 8], b);
            }
        }
    }
}

// ---------------- launch -----------------------------------------------------
extern "C" void kernel_launch(void* const* d_in, const int* in_sizes, int n_in,
                              void* d_out, int out_size) {
    (void)in_sizes; (void)n_in; (void)out_size;
    const float* u      = (const float*)d_in[0];
    const float* v      = (const float*)d_in[1];
    const float* ln_u_w = (const float*)d_in[2];
    const float* ln_u_b = (const float*)d_in[3];
    const float* ln_v_w = (const float*)d_in[4];
    const float* ln_v_b = (const float*)d_in[5];
    const float* W_u    = (const float*)d_in[6];
    const float* b_u    = (const float*)d_in[7];
    const float* W_v    = (const float*)d_in[8];
    const float* b_v    = (const float*)d_in[9];
    float* out = (float*)d_out;

    void *pAu, *pAv, *pWtu, *pWtv;
    cudaGetSymbolAddress(&pAu, g_Au);
    cudaGetSymbolAddress(&pAv, g_Av);
    cudaGetSymbolAddress(&pWtu, g_Wtu);
    cudaGetSymbolAddress(&pWtv, g_Wtv);

    zero_kernel<<<BATCH / 256, 256>>>(out);

    dim3 tgrid(DIM / 32, DIM / 32), tblk(32, 8);
    transpose_convert_kernel<<<tgrid, tblk>>>(W_u, (__nv_bfloat16*)pWtu);
    transpose_convert_kernel<<<tgrid, tblk>>>(W_v, (__nv_bfloat16*)pWtv);

    ln_kernel<<<BATCH, 256>>>(u, ln_u_w, ln_u_b, (__nv_bfloat16*)pAu);
    ln_kernel<<<BATCH, 256>>>(v, ln_v_w, ln_v_b, (__nv_bfloat16*)pAv);

    cudaFuncSetAttribute(fused_gemm_kernel,
                         cudaFuncAttributeMaxDynamicSharedMemorySize, SMEM_DYN);
    fused_gemm_kernel<<<dim3(DIM / BN, BATCH / BM), 512, SMEM_DYN>>>(b_u, b_v, out);
}